// round 5
// baseline (speedup 1.0000x reference)
#include <cuda_runtime.h>
#include <cuda_bf16.h>
#include <cstdint>

#define B_DIM   8192
#define IN_DIM  4096
#define OUT_DIM 4096

// ---------------- scratch (device globals; no allocations allowed) ----------------
__device__ float g_alpha[IN_DIM];
__device__ float g_delta[IN_DIM];
__device__ __nv_bfloat16 g_sT[(size_t)OUT_DIM * IN_DIM];   // sT[n][k] = s[k][n], 32MB
__device__ __nv_bfloat16 g_xhi[(size_t)B_DIM * IN_DIM];    // 64MB
__device__ __nv_bfloat16 g_xlo[(size_t)B_DIM * IN_DIM];    // 64MB

// ---------------- kernel 1: per-input-row delta & alpha ----------------
__global__ void stats_kernel(const float* __restrict__ w) {
    int i = blockIdx.x;
    const float* row = w + (size_t)i * OUT_DIM;
    int tid = threadIdx.x;

    float s = 0.f;
    for (int j = tid; j < OUT_DIM; j += 256) s += fabsf(row[j]);

    __shared__ float red[256];
    __shared__ float redc[256];
    red[tid] = s; __syncthreads();
    for (int k = 128; k > 0; k >>= 1) {
        if (tid < k) red[tid] += red[tid + k];
        __syncthreads();
    }
    __shared__ float deltaS;
    if (tid == 0) deltaS = (0.7f / OUT_DIM) * red[0];
    __syncthreads();
    float delta = deltaS;

    float cnt = 0.f, asum = 0.f;
    for (int j = tid; j < OUT_DIM; j += 256) {
        float a = fabsf(row[j]);
        if (a > delta) { cnt += 1.f; asum += a; }
    }
    red[tid] = asum; redc[tid] = cnt; __syncthreads();
    for (int k = 128; k > 0; k >>= 1) {
        if (tid < k) { red[tid] += red[tid + k]; redc[tid] += redc[tid + k]; }
        __syncthreads();
    }
    if (tid == 0) {
        g_delta[i] = delta;
        float c = redc[0];
        g_alpha[i] = (c > 0.f) ? red[0] / c : 0.f;
    }
}

// ---------------- kernel 2: ternarize + transpose to sT[n][k] ----------------
__global__ void tern_kernel(const float* __restrict__ w) {
    __shared__ __nv_bfloat16 tile[32][33];
    int j = blockIdx.x * 32 + threadIdx.x;   // out dim (contiguous in w)
    int i = blockIdx.y * 32 + threadIdx.y;   // in dim
    float delta = g_delta[i];
    float v = w[(size_t)i * OUT_DIM + j];
    float s = (v > delta) ? 1.f : ((v < -delta) ? -1.f : 0.f);
    tile[threadIdx.y][threadIdx.x] = __float2bfloat16(s);
    __syncthreads();
    int jo = blockIdx.x * 32 + threadIdx.y;
    int io = blockIdx.y * 32 + threadIdx.x;
    g_sT[(size_t)jo * IN_DIM + io] = tile[threadIdx.x][threadIdx.y];
}

// ---------------- kernel 3: x' = x*alpha, split into bf16 hi/lo planes ----------------
__global__ void split_kernel(const float* __restrict__ x) {
    size_t idx4 = (size_t)blockIdx.x * 256 + threadIdx.x;
    size_t base = idx4 * 4;
    int col = (int)(base % IN_DIM);
    float4 xv = *(const float4*)(x + base);
    float4 av = *(const float4*)(g_alpha + col);
    float p0 = xv.x * av.x, p1 = xv.y * av.y, p2 = xv.z * av.z, p3 = xv.w * av.w;
    __nv_bfloat16 h0 = __float2bfloat16(p0);
    __nv_bfloat16 h1 = __float2bfloat16(p1);
    __nv_bfloat16 h2 = __float2bfloat16(p2);
    __nv_bfloat16 h3 = __float2bfloat16(p3);
    __nv_bfloat16 l0 = __float2bfloat16(p0 - __bfloat162float(h0));
    __nv_bfloat16 l1 = __float2bfloat16(p1 - __bfloat162float(h1));
    __nv_bfloat16 l2 = __float2bfloat16(p2 - __bfloat162float(h2));
    __nv_bfloat16 l3 = __float2bfloat16(p3 - __bfloat162float(h3));
    __nv_bfloat162* ph = (__nv_bfloat162*)(g_xhi + base);
    __nv_bfloat162* pl = (__nv_bfloat162*)(g_xlo + base);
    ph[0] = __nv_bfloat162(h0, h1); ph[1] = __nv_bfloat162(h2, h3);
    pl[0] = __nv_bfloat162(l0, l1); pl[1] = __nv_bfloat162(l2, l3);
}

// ---------------- kernel 4: GEMM out = xhi@sT' + xlo@sT' + bias ----------------
#define BM 128
#define BN 128
#define BKT 32
#define LDS 40                       // halves per smem row (32 + 8 pad) -> conflict-free
#define STAGE_HALVES (128 * LDS)     // 5120 halves per tile-stage
#define SMEM_BYTES (6 * STAGE_HALVES * 2)   // Ahi[2] Alo[2] B[2] = 61440 B

__device__ __forceinline__ void cp16(__nv_bfloat16* dst, const __nv_bfloat16* src) {
    uint32_t d = (uint32_t)__cvta_generic_to_shared(dst);
    asm volatile("cp.async.cg.shared.global [%0], [%1], 16;\n" :: "r"(d), "l"(src));
}

__global__ __launch_bounds__(256, 2)
void gemm_kernel(const float* __restrict__ bias, float* __restrict__ out) {
    extern __shared__ __nv_bfloat16 sm[];
    __nv_bfloat16* sAhi = sm;
    __nv_bfloat16* sAlo = sm + 2 * STAGE_HALVES;
    __nv_bfloat16* sB   = sm + 4 * STAGE_HALVES;

    int tid = threadIdx.x;
    int m0 = blockIdx.y * BM;
    int n0 = blockIdx.x * BN;

    int warp = tid >> 5, lane = tid & 31;
    int wm = warp >> 2;          // 0..1 (64 rows each)
    int wn = warp & 3;           // 0..3 (32 cols each)
    int g  = lane >> 2;          // 0..7
    int tg = lane & 3;           // 0..3

    float acc[4][4][4];
    #pragma unroll
    for (int a = 0; a < 4; a++)
        #pragma unroll
        for (int b = 0; b < 4; b++)
            #pragma unroll
            for (int c = 0; c < 4; c++) acc[a][b][c] = 0.f;

    const int KT = IN_DIM / BKT;   // 128 k-tiles

    // ---- stage loader (16B cp.async chunks; 512 chunks/array/tile, 2/thread) ----
    #define LOAD_STAGE(stg, kt)                                               \
    {                                                                         \
        int k0 = (kt) * BKT;                                                  \
        _Pragma("unroll")                                                     \
        for (int t = 0; t < 2; t++) {                                         \
            int chunk = tid + t * 256;                                        \
            int row = chunk >> 2, c16 = chunk & 3;                            \
            int soff = (stg) * STAGE_HALVES + row * LDS + c16 * 8;            \
            size_t ga = (size_t)(m0 + row) * IN_DIM + k0 + c16 * 8;           \
            cp16(sAhi + soff, g_xhi + ga);                                    \
            cp16(sAlo + soff, g_xlo + ga);                                    \
            size_t gb = (size_t)(n0 + row) * IN_DIM + k0 + c16 * 8;           \
            cp16(sB + soff, g_sT + gb);                                       \
        }                                                                     \
        asm volatile("cp.async.commit_group;\n" ::: "memory");                \
    }

    LOAD_STAGE(0, 0);
    int cur = 0;
    for (int kt = 0; kt < KT; kt++) {
        if (kt + 1 < KT) {
            LOAD_STAGE(cur ^ 1, kt + 1);
            asm volatile("cp.async.wait_group 1;\n" ::: "memory");
        } else {
            asm volatile("cp.async.wait_group 0;\n" ::: "memory");
        }
        __syncthreads();

        const __nv_bfloat16* Ah = sAhi + cur * STAGE_HALVES;
        const __nv_bfloat16* Al = sAlo + cur * STAGE_HALVES;
        const __nv_bfloat16* Bs = sB   + cur * STAGE_HALVES;

        #pragma unroll
        for (int kk = 0; kk < BKT; kk += 16) {
            uint32_t bfr[4][2];
            #pragma unroll
            for (int nt = 0; nt < 4; nt++) {
                const __nv_bfloat16* bp = Bs + (wn * 32 + nt * 8 + g) * LDS + kk;
                bfr[nt][0] = *(const uint32_t*)(bp + 2 * tg);
                bfr[nt][1] = *(const uint32_t*)(bp + 8 + 2 * tg);
            }
            #pragma unroll
            for (int half = 0; half < 2; half++) {
                const __nv_bfloat16* As = half ? Al : Ah;
                #pragma unroll
                for (int mt = 0; mt < 4; mt++) {
                    const __nv_bfloat16* ap = As + (wm * 64 + mt * 16 + g) * LDS + kk;
                    uint32_t a0 = *(const uint32_t*)(ap + 2 * tg);
                    uint32_t a1 = *(const uint32_t*)(ap + 8 * LDS + 2 * tg);
                    uint32_t a2 = *(const uint32_t*)(ap + 8 + 2 * tg);
                    uint32_t a3 = *(const uint32_t*)(ap + 8 * LDS + 8 + 2 * tg);
                    #pragma unroll
                    for (int nt = 0; nt < 4; nt++) {
                        asm volatile(
                            "mma.sync.aligned.m16n8k16.row.col.f32.bf16.bf16.f32 "
                            "{%0,%1,%2,%3}, {%4,%5,%6,%7}, {%8,%9}, {%0,%1,%2,%3};\n"
                            : "+f"(acc[mt][nt][0]), "+f"(acc[mt][nt][1]),
                              "+f"(acc[mt][nt][2]), "+f"(acc[mt][nt][3])
                            : "r"(a0), "r"(a1), "r"(a2), "r"(a3),
                              "r"(bfr[nt][0]), "r"(bfr[nt][1]));
                    }
                }
            }
        }
        __syncthreads();
        cur ^= 1;
    }

    // ---- epilogue: + bias, fp32 out (8B stores) ----
    #pragma unroll
    for (int mt = 0; mt < 4; mt++) {
        int r0 = m0 + wm * 64 + mt * 16 + g;
        #pragma unroll
        for (int nt = 0; nt < 4; nt++) {
            int c0 = n0 + wn * 32 + nt * 8 + 2 * tg;
            float b0v = bias[c0], b1v = bias[c0 + 1];
            float2 v0; v0.x = acc[mt][nt][0] + b0v; v0.y = acc[mt][nt][1] + b1v;
            float2 v1; v1.x = acc[mt][nt][2] + b0v; v1.y = acc[mt][nt][3] + b1v;
            *(float2*)(out + (size_t)r0 * OUT_DIM + c0)       = v0;
            *(float2*)(out + (size_t)(r0 + 8) * OUT_DIM + c0) = v1;
        }
    }
}

// ---------------- launch ----------------
extern "C" void kernel_launch(void* const* d_in, const int* in_sizes, int n_in,
                              void* d_out, int out_size) {
    const float* x    = (const float*)d_in[0];
    const float* w    = (const float*)d_in[1];
    const float* bias = (const float*)d_in[2];
    float* out = (float*)d_out;

    stats_kernel<<<IN_DIM, 256>>>(w);
    tern_kernel<<<dim3(OUT_DIM / 32, IN_DIM / 32), dim3(32, 32)>>>(w);
    split_kernel<<<(B_DIM * (IN_DIM / 4)) / 256, 256>>>(x);

    cudaFuncSetAttribute(gemm_kernel,
                         cudaFuncAttributeMaxDynamicSharedMemorySize, SMEM_BYTES);
    gemm_kernel<<<dim3(OUT_DIM / BN, B_DIM / BM), 256, SMEM_BYTES>>>(bias, out);
}

// round 10
// speedup vs baseline: 1.7396x; 1.7396x over previous
#include <cuda_runtime.h>
#include <cuda_fp16.h>
#include <cstdint>

#define B_DIM   8192
#define IN_DIM  4096
#define OUT_DIM 4096

// ---------------- scratch (device globals; no allocations allowed) ----------------
__device__ float g_alpha[IN_DIM];
__device__ float g_delta[IN_DIM];
__device__ __half g_sT[(size_t)OUT_DIM * IN_DIM];   // sT[n][k] = s[k][n], fp16 {-1,0,1}
__device__ __half g_y[(size_t)B_DIM * IN_DIM];      // y = x * alpha, fp16

// ---------------- kernel 1: per-input-row delta & alpha ----------------
__global__ void stats_kernel(const float* __restrict__ w) {
    int i = blockIdx.x;
    const float* row = w + (size_t)i * OUT_DIM;
    int tid = threadIdx.x;

    float s = 0.f;
    for (int j = tid; j < OUT_DIM; j += 256) s += fabsf(row[j]);

    __shared__ float red[256];
    __shared__ float redc[256];
    red[tid] = s; __syncthreads();
    for (int k = 128; k > 0; k >>= 1) {
        if (tid < k) red[tid] += red[tid + k];
        __syncthreads();
    }
    __shared__ float deltaS;
    if (tid == 0) deltaS = (0.7f / OUT_DIM) * red[0];
    __syncthreads();
    float delta = deltaS;

    float cnt = 0.f, asum = 0.f;
    for (int j = tid; j < OUT_DIM; j += 256) {
        float a = fabsf(row[j]);
        if (a > delta) { cnt += 1.f; asum += a; }
    }
    red[tid] = asum; redc[tid] = cnt; __syncthreads();
    for (int k = 128; k > 0; k >>= 1) {
        if (tid < k) { red[tid] += red[tid + k]; redc[tid] += redc[tid + k]; }
        __syncthreads();
    }
    if (tid == 0) {
        g_delta[i] = delta;
        float c = redc[0];
        g_alpha[i] = (c > 0.f) ? red[0] / c : 0.f;
    }
}

// ---------------- kernel 2: ternarize + transpose to sT[n][k] (fp16) ----------------
__global__ void tern_kernel(const float* __restrict__ w) {
    __shared__ __half tile[32][33];
    int j = blockIdx.x * 32 + threadIdx.x;   // out dim (contiguous in w)
    int i = blockIdx.y * 32 + threadIdx.y;   // in dim
    float delta = g_delta[i];
    float v = w[(size_t)i * OUT_DIM + j];
    float s = (v > delta) ? 1.f : ((v < -delta) ? -1.f : 0.f);
    tile[threadIdx.y][threadIdx.x] = __float2half(s);
    __syncthreads();
    int jo = blockIdx.x * 32 + threadIdx.y;
    int io = blockIdx.y * 32 + threadIdx.x;
    g_sT[(size_t)jo * IN_DIM + io] = tile[threadIdx.x][threadIdx.y];
}

// ---------------- kernel 3: y = x*alpha -> fp16 (single plane) ----------------
__global__ void scale_kernel(const float* __restrict__ x) {
    size_t idx4 = (size_t)blockIdx.x * 256 + threadIdx.x;
    size_t base = idx4 * 4;
    int col = (int)(base % IN_DIM);
    float4 xv = *(const float4*)(x + base);
    float4 av = *(const float4*)(g_alpha + col);
    __half2 h01 = __floats2half2_rn(xv.x * av.x, xv.y * av.y);
    __half2 h23 = __floats2half2_rn(xv.z * av.z, xv.w * av.w);
    __half2* py = (__half2*)(g_y + base);
    py[0] = h01; py[1] = h23;
}

// ---------------- kernel 4: GEMM out = y@sT' + bias (fp16 HMMA + ldmatrix) ----------------
#define BM 128
#define BN 128
#define BKT 32
#define LDS 40                       // halves per smem row (32 + 8 pad) -> conflict-free
#define STAGE_H (128 * LDS)          // 5120 halves per tile-stage

__device__ __forceinline__ uint32_t smem_u32(const void* p) {
    uint32_t a;
    asm("{ .reg .u64 t; cvta.to.shared.u64 t, %1; cvt.u32.u64 %0, t; }" : "=r"(a) : "l"(p));
    return a;
}
__device__ __forceinline__ void cp16(uint32_t sdst, const __half* src) {
    asm volatile("cp.async.cg.shared.global [%0], [%1], 16;\n" :: "r"(sdst), "l"(src));
}
__device__ __forceinline__ void ldsm4(uint32_t& r0, uint32_t& r1, uint32_t& r2, uint32_t& r3,
                                      uint32_t addr) {
    asm volatile("ldmatrix.sync.aligned.m8n8.x4.shared.b16 {%0,%1,%2,%3}, [%4];"
                 : "=r"(r0), "=r"(r1), "=r"(r2), "=r"(r3) : "r"(addr));
}

__global__ __launch_bounds__(256, 2)
void gemm_kernel(const float* __restrict__ bias, float* __restrict__ out) {
    __shared__ __half sA[2 * STAGE_H];
    __shared__ __half sB[2 * STAGE_H];

    int tid = threadIdx.x;
    int m0 = blockIdx.y * BM;
    int n0 = blockIdx.x * BN;

    int warp = tid >> 5, lane = tid & 31;
    int wm = warp >> 2;          // 0..1 (64 rows each)
    int wn = warp & 3;           // 0..3 (32 cols each)
    int g  = lane >> 2;          // 0..7
    int tg = lane & 3;           // 0..3

    uint32_t sAu = smem_u32(sA);
    uint32_t sBu = smem_u32(sB);

    // ldmatrix per-lane source rows/cols (in halves, relative to tile origin)
    // A x4 (per mt): m0=rows0-7@k0, m1=rows8-15@k0, m2=rows0-7@k8, m3=rows8-15@k8
    int a_row = (lane & 15);               // 0..15
    int a_kh  = (lane >> 4) * 8;           // 0 or 8
    // B x4 (per nt-pair p): m0=n(2p)rows@k0, m1=n(2p)rows@k8, m2=n(2p+1)rows@k0, m3=n(2p+1)rows@k8
    int b_row = ((lane >> 4) ? 8 : 0) + (lane & 7);   // 0..15 within pair
    int b_kh  = ((lane >> 3) & 1) * 8;     // 0 or 8

    float acc[4][4][4];
    #pragma unroll
    for (int a = 0; a < 4; a++)
        #pragma unroll
        for (int b = 0; b < 4; b++)
            #pragma unroll
            for (int c = 0; c < 4; c++) acc[a][b][c] = 0.f;

    const int KT = IN_DIM / BKT;   // 128 k-tiles

    // stage loader: 512 16B-chunks per array, 2 per thread per array
    #define LOAD_STAGE(stg, kt)                                               \
    {                                                                         \
        int k0 = (kt) * BKT;                                                  \
        _Pragma("unroll")                                                     \
        for (int t = 0; t < 2; t++) {                                         \
            int chunk = tid + t * 256;                                        \
            int row = chunk >> 2, c16 = chunk & 3;                            \
            uint32_t soff = ((stg) * STAGE_H + row * LDS + c16 * 8) * 2;      \
            cp16(sAu + soff, g_y  + (size_t)(m0 + row) * IN_DIM + k0 + c16 * 8); \
            cp16(sBu + soff, g_sT + (size_t)(n0 + row) * IN_DIM + k0 + c16 * 8); \
        }                                                                     \
        asm volatile("cp.async.commit_group;\n" ::: "memory");                \
    }

    LOAD_STAGE(0, 0);
    int cur = 0;
    for (int kt = 0; kt < KT; kt++) {
        if (kt + 1 < KT) {
            LOAD_STAGE(cur ^ 1, kt + 1);
            asm volatile("cp.async.wait_group 1;\n" ::: "memory");
        } else {
            asm volatile("cp.async.wait_group 0;\n" ::: "memory");
        }
        __syncthreads();

        uint32_t Au = sAu + (uint32_t)(cur * STAGE_H) * 2;
        uint32_t Bu = sBu + (uint32_t)(cur * STAGE_H) * 2;

        #pragma unroll
        for (int kk = 0; kk < BKT; kk += 16) {
            // B fragments: 2 x ldmatrix.x4 (each covers 2 nt subtiles)
            uint32_t bfr[4][2];
            #pragma unroll
            for (int p = 0; p < 2; p++) {
                uint32_t addr = Bu + ((wn * 32 + p * 16 + b_row) * LDS + kk + b_kh) * 2;
                ldsm4(bfr[2 * p][0], bfr[2 * p][1], bfr[2 * p + 1][0], bfr[2 * p + 1][1], addr);
            }
            // A fragments + MMAs
            #pragma unroll
            for (int mt = 0; mt < 4; mt++) {
                uint32_t a0, a1, a2, a3;
                uint32_t addr = Au + ((wm * 64 + mt * 16 + a_row) * LDS + kk + a_kh) * 2;
                ldsm4(a0, a1, a2, a3, addr);
                #pragma unroll
                for (int nt = 0; nt < 4; nt++) {
                    asm volatile(
                        "mma.sync.aligned.m16n8k16.row.col.f32.f16.f16.f32 "
                        "{%0,%1,%2,%3}, {%4,%5,%6,%7}, {%8,%9}, {%0,%1,%2,%3};\n"
                        : "+f"(acc[mt][nt][0]), "+f"(acc[mt][nt][1]),
                          "+f"(acc[mt][nt][2]), "+f"(acc[mt][nt][3])
                        : "r"(a0), "r"(a1), "r"(a2), "r"(a3),
                          "r"(bfr[nt][0]), "r"(bfr[nt][1]));
                }
            }
        }
        __syncthreads();
        cur ^= 1;
    }

    // ---- epilogue: + bias, fp32 out (8B stores) ----
    #pragma unroll
    for (int mt = 0; mt < 4; mt++) {
        int r0 = m0 + wm * 64 + mt * 16 + g;
        #pragma unroll
        for (int nt = 0; nt < 4; nt++) {
            int c0 = n0 + wn * 32 + nt * 8 + 2 * tg;
            float b0v = bias[c0], b1v = bias[c0 + 1];
            float2 v0; v0.x = acc[mt][nt][0] + b0v; v0.y = acc[mt][nt][1] + b1v;
            float2 v1; v1.x = acc[mt][nt][2] + b0v; v1.y = acc[mt][nt][3] + b1v;
            *(float2*)(out + (size_t)r0 * OUT_DIM + c0)       = v0;
            *(float2*)(out + (size_t)(r0 + 8) * OUT_DIM + c0) = v1;
        }
    }
}

// ---------------- launch ----------------
extern "C" void kernel_launch(void* const* d_in, const int* in_sizes, int n_in,
                              void* d_out, int out_size) {
    const float* x    = (const float*)d_in[0];
    const float* w    = (const float*)d_in[1];
    const float* bias = (const float*)d_in[2];
    float* out = (float*)d_out;

    stats_kernel<<<IN_DIM, 256>>>(w);
    tern_kernel<<<dim3(OUT_DIM / 32, IN_DIM / 32), dim3(32, 32)>>>(w);
    scale_kernel<<<(B_DIM * (IN_DIM / 4)) / 256, 256>>>(x);

    gemm_kernel<<<dim3(OUT_DIM / BN, B_DIM / BM), 256>>>(bias, out);
}